// round 14
// baseline (speedup 1.0000x reference)
#include <cuda_runtime.h>
#include <cstdint>
#include <cstddef>

// Problem constants
#define VOCAB 50000
#define BB 4096
#define SS 128
#define DD 256
#define CC 5

#define ROWS 32            // batch rows per CTA
#define NTHREADS 256       // 8 warps
#define NGRID (BB / ROWS)  // 128 CTAs
#define HS 36              // padded stride (floats) of k-major SMEM tiles
#define KB 8               // k-block size for streamed weight pipeline
#define WC 152             // weight k-rows cached in SMEM (rest streamed from L2)
#define KSTREAM (DD - WC)  // 104 streamed k-rows
#define NKB (KSTREAM / KB) // 13 blocks

// Device globals (static allocation only).
__device__ __align__(16) float g_Whh_t[DD * DD];   // Whh_t[k][j] = W_hh[j][k]
__device__ __align__(16) float g_Wih_t[DD * DD];   // Wih_t[k][j] = W_ih[j][k]
__device__ __align__(16) float g_bias[DD];         // b_ih + b_hh
__device__ __align__(16) float g_E2[VOCAB * DD];   // E' = emb @ W_ih^T + bias

// ---------- f32x2 packed-FMA helpers (sm_103a) ----------
__device__ __forceinline__ unsigned long long pack2(float x, float y) {
    unsigned long long r;
    asm("mov.b64 %0, {%1,%2};" : "=l"(r) : "f"(x), "f"(y));
    return r;
}
__device__ __forceinline__ void fma2(unsigned long long& d, unsigned long long a, unsigned long long b) {
    asm("fma.rn.f32x2 %0, %1, %2, %0;" : "+l"(d) : "l"(a), "l"(b));
}
__device__ __forceinline__ float2 unpack2(unsigned long long v) {
    float2 r;
    asm("mov.b64 {%0,%1}, %2;" : "=f"(r.x), "=f"(r.y) : "l"(v));
    return r;
}

// Fast accurate tanh: 1 - 2/(e^{2x}+1). abs err ~1e-6, far inside 1e-3 budget.
__device__ __forceinline__ float fast_tanh(float x) {
    x = fminf(fmaxf(x, -10.0f), 10.0f);
    float e = __expf(2.0f * x);
    return 1.0f - __fdividef(2.0f, e + 1.0f);
}

// ---------- mbarrier helpers ----------
__device__ __forceinline__ uint32_t smem_u32(const void* p) {
    uint32_t a;
    asm("{ .reg .u64 t; cvta.to.shared.u64 t, %1; cvt.u32.u64 %0, t; }" : "=r"(a) : "l"(p));
    return a;
}
__device__ __forceinline__ void mbar_init(uint32_t addr, uint32_t count) {
    asm volatile("mbarrier.init.shared.b64 [%0], %1;" :: "r"(addr), "r"(count) : "memory");
}
__device__ __forceinline__ void mbar_arrive(uint32_t addr) {
    asm volatile("mbarrier.arrive.release.cta.shared::cta.b64 _, [%0];" :: "r"(addr) : "memory");
}
__device__ __forceinline__ void mbar_wait(uint32_t addr, uint32_t parity) {
    uint32_t done;
    asm volatile(
        "{\n\t.reg .pred p;\n\t"
        "mbarrier.try_wait.parity.acquire.cta.shared::cta.b64 p, [%1], %2;\n\t"
        "selp.b32 %0, 1, 0, p;\n\t}"
        : "=r"(done) : "r"(addr), "r"(parity) : "memory");
    if (!done) {
        asm volatile(
            "{\n\t.reg .pred P1;\n\t"
            "WAIT_LOOP_%=:\n\t"
            "mbarrier.try_wait.parity.acquire.cta.shared::cta.b64 P1, [%0], %1, 0x989680;\n\t"
            "@P1 bra.uni WAIT_DONE_%=;\n\t"
            "bra.uni WAIT_LOOP_%=;\n\t"
            "WAIT_DONE_%=:\n\t}"
            :: "r"(addr), "r"(parity) : "memory");
    }
}

// ---------- prep1: transpose weights, fuse biases ----------
__global__ void prep_kernel(const float* __restrict__ W_ih,
                            const float* __restrict__ W_hh,
                            const float* __restrict__ b_ih,
                            const float* __restrict__ b_hh) {
    int k = blockIdx.x;   // 0..255
    int j = threadIdx.x;  // 0..255
    g_Whh_t[k * DD + j] = W_hh[j * DD + k];
    g_Wih_t[k * DD + j] = W_ih[j * DD + k];
    if (k == 0) g_bias[j] = b_ih[j] + b_hh[j];
}

// ---------- prep2: E' = emb @ W_ih^T + bias, persistent weight-resident ----------
#define NTILES ((VOCAB + ROWS - 1) / ROWS)   // 1563
#define EG_GRID 296
#define EG_JC 128                             // cols per CTA

#define EG_SMEM_FLOATS (DD * EG_JC + DD * HS)
#define EG_SMEM_BYTES  (EG_SMEM_FLOATS * 4)

__global__ void __launch_bounds__(NTHREADS, 1)
egemm_kernel(const float* __restrict__ emb) {
    extern __shared__ float esm[];
    float* wsW  = esm;                 // DD*EG_JC, k-major rows of 128 cols
    float* xe_s = esm + DD * EG_JC;    // DD*HS

    const int tid  = threadIdx.x;
    const int lane = tid & 31;
    const int warp = tid >> 5;
    const int part = blockIdx.x >> 1;        // 0..147
    const int jh   = blockIdx.x & 1;         // 0/1
    const int jbase = jh * EG_JC;

    const int r0 = (warp >> 1) * 8;
    const int jj = (warp & 1) * 64 + lane * 2;   // col within 128-slice

    const int g_row = tid >> 3;     // 0..31 (gather: 8 threads/row)
    const int g_sub = tid & 7;

    // bias for this thread's 2 cols (folded into E')
    const float2 b2 = *(const float2*)(g_bias + jbase + jj);
    const unsigned long long bx = pack2(b2.x, b2.x);
    const unsigned long long by = pack2(b2.y, b2.y);

    // ---- one-time: load this CTA's weight slice into SMEM ----
    for (int idx = tid * 4; idx < DD * EG_JC; idx += NTHREADS * 4) {
        int k = idx >> 7;           // /128
        int c = idx & 127;
        *(float4*)(wsW + idx) = *(const float4*)(g_Wih_t + k * DD + jbase + c);
    }
    __syncthreads();

    for (int tile = part; tile < NTILES; tile += 148) {
        const int v0 = tile * ROWS;

        // ---- gather emb tile (k-major); clamp OOB rows to row 0 ----
        {
            int v = v0 + g_row;
            if (v >= VOCAB) v = 0;
            const float* erow = emb + (size_t)v * DD;
            #pragma unroll
            for (int i = 0; i < 8; i++) {
                float4 vv = *(const float4*)(erow + i * 32 + g_sub * 4);
                int c0 = i * 32 + g_sub * 4;
                xe_s[(c0 + 0) * HS + g_row] = vv.x;
                xe_s[(c0 + 1) * HS + g_row] = vv.y;
                xe_s[(c0 + 2) * HS + g_row] = vv.z;
                xe_s[(c0 + 3) * HS + g_row] = vv.w;
            }
        }
        __syncthreads();

        // ---- GEMM: all weights from SMEM; acc starts at bias ----
        unsigned long long acc[4][2];
        #pragma unroll
        for (int p = 0; p < 4; p++) { acc[p][0] = bx; acc[p][1] = by; }

        #pragma unroll 8
        for (int k = 0; k < DD; k++) {
            float2 w = *(const float2*)(wsW + (k << 7) + jj);            // LDS.64
            ulonglong2 aA = *(const ulonglong2*)(xe_s + k * HS + r0);
            ulonglong2 aB = *(const ulonglong2*)(xe_s + k * HS + r0 + 4);
            unsigned long long w0 = pack2(w.x, w.x);
            unsigned long long w1 = pack2(w.y, w.y);
            fma2(acc[0][0], aA.x, w0); fma2(acc[0][1], aA.x, w1);
            fma2(acc[1][0], aA.y, w0); fma2(acc[1][1], aA.y, w1);
            fma2(acc[2][0], aB.x, w0); fma2(acc[2][1], aB.x, w1);
            fma2(acc[3][0], aB.y, w0); fma2(acc[3][1], aB.y, w1);
        }

        // ---- epilogue: write E2[v][jbase+jj .. +1] ----
        #pragma unroll
        for (int p = 0; p < 4; p++) {
            float2 c0 = unpack2(acc[p][0]);   // (row 2p, row 2p+1) col jj
            float2 c1 = unpack2(acc[p][1]);   // col jj+1
            int va = v0 + r0 + 2 * p;
            int vb = va + 1;
            if (va < VOCAB)
                *(float2*)(g_E2 + (size_t)va * DD + jbase + jj) = make_float2(c0.x, c1.x);
            if (vb < VOCAB)
                *(float2*)(g_E2 + (size_t)vb * DD + jbase + jj) = make_float2(c0.y, c1.y);
        }
        __syncthreads();   // xe_s reads done before next tile's gather
    }
}

// ---------- fused persistent RNN kernel ----------
// SMEM (floats): ws [WC][DD], buf0/buf1 [DD][HS], then 2 mbarriers (16B)
#define BUF_FLOATS (DD * HS)
#define SMEM_FLOATS (WC * DD + 2 * BUF_FLOATS)
#define SMEM_BYTES  (SMEM_FLOATS * 4 + 16)

__global__ void __launch_bounds__(NTHREADS, 1)
rnn_kernel(const int* __restrict__ x,          // int32 (JAX x64-disabled)
           const float* __restrict__ W_cls,
           const float* __restrict__ b_cls,
           float* __restrict__ out) {
    extern __shared__ float smem[];
    float* ws    = smem;                        // WC*DD
    float* buf0  = smem + WC * DD;              // DD*HS
    float* buf1  = buf0 + BUF_FLOATS;           // DD*HS
    const uint32_t mbar_lo = smem_u32(buf1 + BUF_FLOATS);
    const uint32_t mbar_hi = mbar_lo + 8;

    const int tid  = threadIdx.x;
    const int lane = tid & 31;
    const int warp = tid >> 5;
    const int row0 = blockIdx.x * ROWS;
    const int is_odd = warp & 1;               // odd warps own cols 128..255

    // warp tile: 8 rows x 128 cols; thread tile: 8 rows x 4 cols (16 fma2/k)
    const int r0 = (warp >> 1) * 8;                  // 0,8,16,24
    const int j0 = is_odd * 128 + lane * 4;

    // ---- one-time init ----
    if (tid == 0) { mbar_init(mbar_lo, 4); mbar_init(mbar_hi, 4); }
    for (int idx = tid * 4; idx < WC * DD; idx += NTHREADS * 4)
        *(float4*)(ws + idx) = *(const float4*)(g_Whh_t + idx);
    for (int idx = tid; idx < BUF_FLOATS; idx += NTHREADS) buf0[idx] = 0.0f;

    // token base for this thread's 8 rows
    const int* xrow = x + (size_t)(row0 + r0) * SS;

    // ---- prologue: gather E'[tok(0)] (bias included) ----
    float4 xr[8];
    #pragma unroll
    for (int i = 0; i < 8; i++) {
        int tokr = xrow[i * SS + 0];
        xr[i] = *(const float4*)(g_E2 + (size_t)tokr * DD + j0);
    }

    __syncthreads();   // ws, buf0-zero, mbar init all visible

    // pre-loop arrivals (completion 1 -> phase 0), so step-0 waits pass
    if (lane == 0) mbar_arrive(is_odd ? mbar_hi : mbar_lo);

    const float* wstream = g_Whh_t + WC * DD + j0;   // streamed tail base

    for (int t = 0; t < SS; t++) {
        float* cur = (t & 1) ? buf1 : buf0;
        float* nxt = (t & 1) ? buf0 : buf1;
        const uint32_t par = (uint32_t)(t & 1);

        // ---- acc init from E'[tok(t)] (xr consumed, regs freed) ----
        unsigned long long acc[4][4];
        #pragma unroll
        for (int p = 0; p < 4; p++) {
            acc[p][0] = pack2(xr[2 * p].x, xr[2 * p + 1].x);
            acc[p][1] = pack2(xr[2 * p].y, xr[2 * p + 1].y);
            acc[p][2] = pack2(xr[2 * p].z, xr[2 * p + 1].z);
            acc[p][3] = pack2(xr[2 * p].w, xr[2 * p + 1].w);
        }

        // ---- h-independent loads BEFORE the waits (overlap wait latency) ----
        float4 wcv[KB], wnv[KB];
        #pragma unroll
        for (int i = 0; i < KB; i++) wcv[i] = *(const float4*)(wstream + i * DD);
        {
            int tn = (t + 1 < SS) ? (t + 1) : t;
            int tk[8];
            #pragma unroll
            for (int i = 0; i < 8; i++) tk[i] = xrow[i * SS + tn];
            #pragma unroll
            for (int i = 0; i < 8; i++)
                xr[i] = *(const float4*)(g_E2 + (size_t)tk[i] * DD + j0);
        }

        // ---- wait for lo-half h (cols 0..127, even warps' commits) ----
        mbar_wait(mbar_lo, par);

        // ---- GEMM lo: k = 0..127, cached weights ----
        #pragma unroll 8
        for (int k = 0; k < 128; k++) {
            float4 w = *(const float4*)(ws + (k << 8) + j0);          // LDS.128
            ulonglong2 aA = *(const ulonglong2*)(cur + k * HS + r0);
            ulonglong2 aB = *(const ulonglong2*)(cur + k * HS + r0 + 4);
            unsigned long long w0 = pack2(w.x, w.x);
            unsigned long long w1 = pack2(w.y, w.y);
            unsigned long long w2 = pack2(w.z, w.z);
            unsigned long long w3 = pack2(w.w, w.w);
            fma2(acc[0][0], aA.x, w0); fma2(acc[0][1], aA.x, w1);
            fma2(acc[0][2], aA.x, w2); fma2(acc[0][3], aA.x, w3);
            fma2(acc[1][0], aA.y, w0); fma2(acc[1][1], aA.y, w1);
            fma2(acc[1][2], aA.y, w2); fma2(acc[1][3], aA.y, w3);
            fma2(acc[2][0], aB.x, w0); fma2(acc[2][1], aB.x, w1);
            fma2(acc[2][2], aB.x, w2); fma2(acc[2][3], aB.x, w3);
            fma2(acc[3][0], aB.y, w0); fma2(acc[3][1], aB.y, w1);
            fma2(acc[3][2], aB.y, w2); fma2(acc[3][3], aB.y, w3);
        }

        // ---- wait for hi-half h (cols 128..255, odd warps' commits) ----
        mbar_wait(mbar_hi, par);

        // ---- GEMM hi-cached: k = 128..WC-1 ----
        #pragma unroll 8
        for (int k = 128; k < WC; k++) {
            float4 w = *(const float4*)(ws + (k << 8) + j0);
            ulonglong2 aA = *(const ulonglong2*)(cur + k * HS + r0);
            ulonglong2 aB = *(const ulonglong2*)(cur + k * HS + r0 + 4);
            unsigned long long w0 = pack2(w.x, w.x);
            unsigned long long w1 = pack2(w.y, w.y);
            unsigned long long w2 = pack2(w.z, w.z);
            unsigned long long w3 = pack2(w.w, w.w);
            fma2(acc[0][0], aA.x, w0); fma2(acc[0][1], aA.x, w1);
            fma2(acc[0][2], aA.x, w2); fma2(acc[0][3], aA.x, w3);
            fma2(acc[1][0], aA.y, w0); fma2(acc[1][1], aA.y, w1);
            fma2(acc[1][2], aA.y, w2); fma2(acc[1][3], aA.y, w3);
            fma2(acc[2][0], aB.x, w0); fma2(acc[2][1], aB.x, w1);
            fma2(acc[2][2], aB.x, w2); fma2(acc[2][3], aB.x, w3);
            fma2(acc[3][0], aB.y, w0); fma2(acc[3][1], aB.y, w1);
            fma2(acc[3][2], aB.y, w2); fma2(acc[3][3], aB.y, w3);
        }

        // ---- GEMM hi-streamed: k = WC..255, block-pipelined ----
        #pragma unroll 2
        for (int kb = 0; kb < NKB; kb++) {
            const float* wnx = wstream + ((kb + 1 < NKB) ? (kb + 1) : kb) * (KB * DD);
            #pragma unroll
            for (int i = 0; i < KB; i++) wnv[i] = *(const float4*)(wnx + i * DD);

            const float* abase = cur + (WC + kb * KB) * HS + r0;
            #pragma unroll
            for (int i = 0; i < KB; i++) {
                ulonglong2 aA = *(const ulonglong2*)(abase + i * HS);
                ulonglong2 aB = *(const ulonglong2*)(abase + i * HS + 4);
                unsigned long long w0 = pack2(wcv[i].x, wcv[i].x);
                unsigned long long w1 = pack2(wcv[i].y, wcv[i].y);
                unsigned long long w2 = pack2(wcv[i].z, wcv[i].z);
                unsigned long long w3 = pack2(wcv[i].w, wcv[i].w);
                fma2(acc[0][0], aA.x, w0); fma2(acc[0][1], aA.x, w1);
                fma2(acc[0][2], aA.x, w2); fma2(acc[0][3], aA.x, w3);
                fma2(acc[1][0], aA.y, w0); fma2(acc[1][1], aA.y, w1);
                fma2(acc[1][2], aA.y, w2); fma2(acc[1][3], aA.y, w3);
                fma2(acc[2][0], aB.x, w0); fma2(acc[2][1], aB.x, w1);
                fma2(acc[2][2], aB.x, w2); fma2(acc[2][3], aB.x, w3);
                fma2(acc[3][0], aB.y, w0); fma2(acc[3][1], aB.y, w1);
                fma2(acc[3][2], aB.y, w2); fma2(acc[3][3], aB.y, w3);
            }
            #pragma unroll
            for (int i = 0; i < KB; i++) wcv[i] = wnv[i];
        }

        // ---- tanh + commit (interleaved per col), then arrive own half ----
        #pragma unroll
        for (int c = 0; c < 4; c++) {
            float hv[8];
            #pragma unroll
            for (int p = 0; p < 4; p++) {
                float2 v = unpack2(acc[p][c]);
                hv[2 * p]     = fast_tanh(v.x);
                hv[2 * p + 1] = fast_tanh(v.y);
            }
            float* dst = nxt + (j0 + c) * HS + r0;
            *(float4*)(dst)     = make_float4(hv[0], hv[1], hv[2], hv[3]);
            *(float4*)(dst + 4) = make_float4(hv[4], hv[5], hv[6], hv[7]);
        }
        __syncwarp();
        if (lane == 0) mbar_arrive(is_odd ? mbar_hi : mbar_lo);
    }

    __syncthreads();   // all final commits visible

    // ---- classifier: final h is in buf0 (t=127 wrote nxt=buf0) ----
    if (tid < ROWS * CC) {
        int r = tid / CC;
        int c = tid % CC;
        float s = b_cls[c];
        const float* wc2 = W_cls + c * DD;
        #pragma unroll 8
        for (int d = 0; d < DD; d++) {
            s += buf0[d * HS + r] * wc2[d];
        }
        out[(size_t)(row0 + r) * CC + c] = s;
    }
}

extern "C" void kernel_launch(void* const* d_in, const int* in_sizes, int n_in,
                              void* d_out, int out_size) {
    const int* x         = (const int*)d_in[0];   // int32
    const float* emb     = (const float*)d_in[1];
    const float* W_ih    = (const float*)d_in[2];
    const float* W_hh    = (const float*)d_in[3];
    const float* b_ih    = (const float*)d_in[4];
    const float* b_hh    = (const float*)d_in[5];
    const float* W_cls   = (const float*)d_in[6];
    const float* b_cls   = (const float*)d_in[7];
    float* out = (float*)d_out;

    (void)in_sizes; (void)n_in; (void)out_size;

    cudaFuncSetAttribute(rnn_kernel, cudaFuncAttributeMaxDynamicSharedMemorySize, SMEM_BYTES);
    cudaFuncSetAttribute(egemm_kernel, cudaFuncAttributeMaxDynamicSharedMemorySize, EG_SMEM_BYTES);

    prep_kernel<<<DD, DD>>>(W_ih, W_hh, b_ih, b_hh);
    egemm_kernel<<<EG_GRID, NTHREADS, EG_SMEM_BYTES>>>(emb);
    rnn_kernel<<<NGRID, NTHREADS, SMEM_BYTES>>>(x, W_cls, b_cls, out);
}